// round 1
// baseline (speedup 1.0000x reference)
#include <cuda_runtime.h>

#define H 256
#define DD 64
#define NDIR 6112
#define GDIR 16
#define NBLK (NDIR / GDIR)   // 382

// ---------------- scratch (device globals; no allocations) ----------------
__device__ __align__(16) float g_W1T[DD * H];   // W1T[d*256+n] = W1[n,d]
__device__ __align__(16) float g_W2T[H * H];    // W2T[m*256+n] = W2[n,m]
__device__ __align__(16) float g_c[4 * H];      // layer-1 jet constants c1..c4
__device__ float g_g0[H], g_om0[H];             // layer-2 tanh value / 1-g0^2
__device__ double g_accum;

// ---------------- f32x2 packed-FMA helpers (Blackwell) ----------------
__device__ __forceinline__ unsigned long long pk2(float a, float b) {
    unsigned long long r;
    asm("mov.b64 %0, {%1, %2};" : "=l"(r) : "f"(a), "f"(b));
    return r;
}
__device__ __forceinline__ unsigned long long f2(unsigned long long a,
                                                 unsigned long long b,
                                                 unsigned long long c) {
    unsigned long long d;
    asm("fma.rn.f32x2 %0, %1, %2, %3;" : "=l"(d) : "l"(a), "l"(b), "l"(c));
    return d;
}
__device__ __forceinline__ void up2(unsigned long long v, float& a, float& b) {
    asm("mov.b64 {%0, %1}, %2;" : "=f"(a), "=f"(b) : "l"(v));
}

// ---------------- kernel 1: transposes ----------------
__global__ void k_transpose(const float* __restrict__ W1, const float* __restrict__ W2) {
    int idx = blockIdx.x * 256 + threadIdx.x;
    if (idx < H * H) {
        int m = idx >> 8, n = idx & 255;
        g_W2T[idx] = W2[n * H + m];
    } else {
        int t = idx - H * H;
        if (t < DD * H) {
            int d = t >> 8, n = t & 255;
            g_W1T[t] = W1[n * DD + d];
        }
    }
}

// ---------------- kernel 2: shared point-dependent quantities ----------------
// Layer-1 tanh jets for input jet (x, v, 0, 0, 0) collapse to h_k = c_k * u1^k:
//   c1 = w0
//   c2 = -h0*w0
//   c3 = (1/3) w0 (2 h0^2 - w0)
//   c4 = -(1/3) h0 w0 (h0^2 - 2 w0)
__global__ void k_setup(const float* __restrict__ x, const float* __restrict__ W1,
                        const float* __restrict__ b1, const float* __restrict__ b2) {
    __shared__ float sx[DD];
    __shared__ float sh0[H];
    int n = threadIdx.x;
    if (n < DD) sx[n] = x[n];
    __syncthreads();

    float u0 = b1[n];
#pragma unroll
    for (int d = 0; d < DD; d++) u0 += W1[n * DD + d] * sx[d];
    float h0 = tanhf(u0);
    float w0 = 1.f - h0 * h0;
    g_c[0 * H + n] = w0;
    g_c[1 * H + n] = -h0 * w0;
    g_c[2 * H + n] = w0 * (2.f * h0 * h0 - w0) * (1.f / 3.f);
    g_c[3 * H + n] = -h0 * w0 * (h0 * h0 - 2.f * w0) * (1.f / 3.f);
    sh0[n] = h0;
    __syncthreads();

    float a0 = b2[n];
    for (int m = 0; m < H; m++) a0 += g_W2T[m * H + n] * sh0[m];
    float g0 = tanhf(a0);
    g_g0[n] = g0;
    g_om0[n] = 1.f - g0 * g0;
    if (n == 0) g_accum = 0.0;
}

// ---------------- kernel 3: main fused GEMM + tanh-jet epilogue ----------------
// Block handles 16 directions. smem sH[256 m][64 cols], col = dirLocal*4 + (k-1),
// holding h_k[m] = c_k[m] * u1[m]^k. Then a_k[n] = sum_m W2T[m][n] * sH[m][col],
// computed with f32x2 FMAs (thread tile: 4 n-rows x 16 cols). Epilogue runs the
// order-4 tanh jet recurrence at layer 2 and reduces w3 . g4 per direction.
__global__ __launch_bounds__(256, 2) void k_main(const float* __restrict__ W3) {
    extern __shared__ float sH[];  // 256 * 64 floats = 64 KB
    __shared__ int sI[GDIR], sJ[GDIR];
    __shared__ float sCA[GDIR], sCB[GDIR], sWt[GDIR];

    int tid = threadIdx.x;

    // decode this block's 16 directions
    if (tid < GDIR) {
        int dir = blockIdx.x * GDIR + tid;
        int i, j;
        float cA, cB, wt;  // wt = polarization_weight * 24 (d4 = 24 * Taylor coeff)
        if (dir < 64) {                    // 4*e_i ; alpha*24 = 8.625
            i = dir; j = dir; cA = 4.f; cB = 0.f; wt = 8.625f;
        } else if (dir < 4096) {           // 3*e_i + e_j, i != j ; beta*24 = -2/3
            int p = dir - 64;
            i = p / 63;
            int r = p - i * 63;
            j = r + (r >= i ? 1 : 0);
            cA = 3.f; cB = 1.f; wt = -2.f / 3.f;
        } else {                           // 2*e_i + 2*e_j, i < j ; gamma*24 = 1.25
            int p = dir - 4096;
            int ii = 0;
            while (p >= 63 - ii) { p -= 63 - ii; ii++; }
            i = ii; j = ii + 1 + p;
            cA = 2.f; cB = 2.f; wt = 1.25f;
        }
        sI[tid] = i; sJ[tid] = j; sCA[tid] = cA; sCB[tid] = cB; sWt[tid] = wt;
    }
    __syncthreads();

    // build jet columns: thread handles neuron m = tid for all 16 dirs
    {
        int m = tid;
        float c1 = g_c[0 * H + m], c2 = g_c[1 * H + m];
        float c3 = g_c[2 * H + m], c4 = g_c[3 * H + m];
#pragma unroll
        for (int dL = 0; dL < GDIR; dL++) {
            float u1 = sCA[dL] * g_W1T[sI[dL] * H + m] + sCB[dL] * g_W1T[sJ[dL] * H + m];
            float u2 = u1 * u1;
            *(float4*)(sH + m * 64 + dL * 4) =
                make_float4(c1 * u1, c2 * u2, c3 * u2 * u1, c4 * u2 * u2);
        }
    }
    __syncthreads();

    // GEMM: 256 rows (n) x 64 cols, K=256.  Thread: tn in [0,64) -> n = 4*tn..,
    // tc in [0,4) -> cols 16*tc.. ; acc packed over col pairs.
    int tn = tid & 63, tc = tid >> 6;
    unsigned long long acc[4][8];
#pragma unroll
    for (int a = 0; a < 4; a++)
#pragma unroll
        for (int b = 0; b < 8; b++) acc[a][b] = 0ull;

    const float4* wrow = (const float4*)(g_W2T) + tn;  // row m at wrow[m*64]
#pragma unroll 2
    for (int m = 0; m < H; m++) {
        float4 w = __ldg(wrow + m * 64);
        unsigned long long wd0 = pk2(w.x, w.x), wd1 = pk2(w.y, w.y);
        unsigned long long wd2 = pk2(w.z, w.z), wd3 = pk2(w.w, w.w);
        const ulonglong2* hp = (const ulonglong2*)(sH + m * 64 + tc * 16);
        ulonglong2 hA = hp[0], hB = hp[1], hC = hp[2], hD = hp[3];
        unsigned long long hh[8] = {hA.x, hA.y, hB.x, hB.y, hC.x, hC.y, hD.x, hD.y};
#pragma unroll
        for (int c = 0; c < 8; c++) {
            acc[0][c] = f2(hh[c], wd0, acc[0][c]);
            acc[1][c] = f2(hh[c], wd1, acc[1][c]);
            acc[2][c] = f2(hh[c], wd2, acc[2][c]);
            acc[3][c] = f2(hh[c], wd3, acc[3][c]);
        }
    }

    // epilogue: layer-2 tanh jet recurrence per (neuron, direction)
    float g0v[4], om0v[4], w3v[4];
#pragma unroll
    for (int nl = 0; nl < 4; nl++) {
        int ng = tn * 4 + nl;
        g0v[nl] = g_g0[ng];
        om0v[nl] = g_om0[ng];
        w3v[nl] = W3[ng];
    }
    float local = 0.f;
#pragma unroll
    for (int dL = 0; dL < 4; dL++) {
        float psum = 0.f;
#pragma unroll
        for (int nl = 0; nl < 4; nl++) {
            float a1, a2, a3, a4;
            up2(acc[nl][dL * 2], a1, a2);
            up2(acc[nl][dL * 2 + 1], a3, a4);
            float g0 = g0v[nl], om0 = om0v[nl];
            float g1 = om0 * a1;
            float om1 = -2.f * g0 * g1;
            float g2 = 0.5f * a1 * om1 + a2 * om0;
            float om2 = -(2.f * g0 * g2 + g1 * g1);
            float g3 = (a1 * om2 + 2.f * a2 * om1) * (1.f / 3.f) + a3 * om0;
            float om3 = -2.f * (g0 * g3 + g1 * g2);
            float g4 = 0.25f * (a1 * om3 + 2.f * a2 * om2 + 3.f * a3 * om1) + a4 * om0;
            psum += w3v[nl] * g4;
        }
        local += sWt[tc * 4 + dL] * psum;
    }

    // block reduction (reuse smem), then one double atomic per block
    __syncthreads();
    double* sred = (double*)sH;
    sred[tid] = (double)local;
    __syncthreads();
    for (int s = 128; s > 0; s >>= 1) {
        if (tid < s) sred[tid] += sred[tid + s];
        __syncthreads();
    }
    if (tid == 0) atomicAdd(&g_accum, sred[0]);
}

// ---------------- kernel 4: finalize ----------------
__global__ void k_final(float* out) { out[0] = (float)g_accum; }

// ---------------- launch ----------------
extern "C" void kernel_launch(void* const* d_in, const int* in_sizes, int n_in,
                              void* d_out, int out_size) {
    const float* x  = (const float*)d_in[0];
    const float* W1 = (const float*)d_in[1];
    const float* b1 = (const float*)d_in[2];
    const float* W2 = (const float*)d_in[3];
    const float* b2 = (const float*)d_in[4];
    const float* W3 = (const float*)d_in[5];
    // d_in[6] = b3: does not affect 4th derivative
    float* out = (float*)d_out;

    cudaFuncSetAttribute(k_main, cudaFuncAttributeMaxDynamicSharedMemorySize, 65536);

    k_transpose<<<(H * H + DD * H) / 256, 256>>>(W1, W2);
    k_setup<<<1, 256>>>(x, W1, b1, b2);
    k_main<<<NBLK, 256, 65536>>>(W3);
    k_final<<<1, 1>>>(out);
}